// round 3
// baseline (speedup 1.0000x reference)
#include <cuda_runtime.h>
#include <cuda_bf16.h>
#include <stdint.h>

#define NMAX   100000
#define NB     3200          // bitset words (NMAX/32 rounded up)
#define F_IN   128
#define HDIM   16
#define EMB    100
#define AA     5
#define HID    128
#define L2CAP  400000
#define L3CAP  100000
#define GN     64
#define XPITCH 132

// -------- scratch (device globals) --------
__device__ float g_deg [NMAX];          // deg-sum, then dinv in-place
__device__ float g_h1p [NMAX * HDIM];
__device__ float g_agg1[NMAX * HDIM];
__device__ float g_h2p [NMAX * HDIM];
__device__ float g_agg2[NMAX * HDIM];
__device__ float g_h2  [NMAX * HDIM];
__device__ float g_agg3[AA * HDIM];
__device__ unsigned int g_n1bits[NB];
__device__ unsigned int g_n2bits[NB];
__device__ int g_list2[L2CAP];
__device__ int g_list3[L3CAP];
__device__ int g_nl1[NMAX];
__device__ int g_nl2[NMAX];
__device__ int g_cnt[4];   // [0]=cnt_list2 [1]=cnt_list3 [2]=cnt_nl1 [3]=cnt_nl2

__device__ __forceinline__ void mark2_push(int node) {
    unsigned bit = 1u << (node & 31);
    unsigned old = atomicOr(&g_n2bits[node >> 5], bit);
    if (!(old & bit)) {
        int k = atomicAdd(&g_cnt[3], 1);
        if (k < NMAX) g_nl2[k] = node;
        float4 z = make_float4(0.f, 0.f, 0.f, 0.f);
        float4* p = (float4*)(g_agg2 + node * HDIM);
        p[0] = z; p[1] = z; p[2] = z; p[3] = z;
    }
}

__device__ __forceinline__ void mark1_push(int node) {
    unsigned bit = 1u << (node & 31);
    unsigned old = atomicOr(&g_n1bits[node >> 5], bit);
    if (!(old & bit)) {
        int k = atomicAdd(&g_cnt[2], 1);
        if (k < NMAX) g_nl1[k] = node;
        float4 z = make_float4(0.f, 0.f, 0.f, 0.f);
        float4* p = (float4*)(g_agg1 + node * HDIM);
        p[0] = z; p[1] = z; p[2] = z; p[3] = z;
    }
}

// ======== phase1: gemm (blocks < gemmBlocks) ∪ scan1 (deg + need2 + list3) ========
__global__ __launch_bounds__(256) void k_phase1(
        const float* __restrict__ x, const float* __restrict__ W1,
        const int* __restrict__ src, const int* __restrict__ dst,
        const float* __restrict__ ew, const int* __restrict__ pos,
        int n, int E, int gemmBlocks) {
    __shared__ float xs[GN * XPITCH];
    __shared__ float ws[F_IN * HDIM];
    int t = threadIdx.x;
    int b = blockIdx.x;

    if (b < gemmBlocks) {
        int n0 = b * GN;
#pragma unroll
        for (int k = 0; k < 8; k++) ws[t + k * 256] = W1[t + k * 256];
#pragma unroll
        for (int k = 0; k < 8; k++) {
            int f = t + k * 256;
            int r = f >> 5, c = f & 31;
            float4 v = make_float4(0.f, 0.f, 0.f, 0.f);
            int node = n0 + r;
            if (node < n) v = *(const float4*)(x + (size_t)node * F_IN + c * 4);
            *(float4*)(xs + r * XPITCH + c * 4) = v;
        }
        __syncthreads();
        int r = t >> 2;
        int og = (t & 3) * 4;
        const float* xr = xs + r * XPITCH;
        float4 acc = make_float4(0.f, 0.f, 0.f, 0.f);
#pragma unroll 8
        for (int j = 0; j < F_IN; j += 4) {
            float4 xv = *(const float4*)(xr + j);
            const float* wb = ws + j * HDIM + og;
            float4 w0 = *(const float4*)(wb);
            float4 w1 = *(const float4*)(wb + HDIM);
            float4 w2 = *(const float4*)(wb + 2 * HDIM);
            float4 w3 = *(const float4*)(wb + 3 * HDIM);
            acc.x = fmaf(xv.x, w0.x, acc.x); acc.y = fmaf(xv.x, w0.y, acc.y);
            acc.z = fmaf(xv.x, w0.z, acc.z); acc.w = fmaf(xv.x, w0.w, acc.w);
            acc.x = fmaf(xv.y, w1.x, acc.x); acc.y = fmaf(xv.y, w1.y, acc.y);
            acc.z = fmaf(xv.y, w1.z, acc.z); acc.w = fmaf(xv.y, w1.w, acc.w);
            acc.x = fmaf(xv.z, w2.x, acc.x); acc.y = fmaf(xv.z, w2.y, acc.y);
            acc.z = fmaf(xv.z, w2.z, acc.z); acc.w = fmaf(xv.z, w2.w, acc.w);
            acc.x = fmaf(xv.w, w3.x, acc.x); acc.y = fmaf(xv.w, w3.y, acc.y);
            acc.z = fmaf(xv.w, w3.z, acc.z); acc.w = fmaf(xv.w, w3.w, acc.w);
        }
        int node = n0 + r;
        if (node < n) *(float4*)(g_h1p + node * HDIM + og) = acc;
    } else {
        int bb = b - gemmBlocks;
        int p0 = __ldg(pos + 0), p1 = __ldg(pos + 1), p2 = __ldg(pos + 2),
            p3 = __ldg(pos + 3), p4 = __ldg(pos + 4);
        if (bb == 0 && t < AA) {
            int p = __ldg(pos + t);
            if (p >= 0) mark2_push(p);
        }
        int base = (bb * 256 + t) * 4;
#pragma unroll
        for (int j = 0; j < 4; j++) {
            int e = base + j;
            if (e >= E) break;
            int d = __ldg(dst + e);
            atomicAdd(&g_deg[d], __ldg(ew + e));
            if (d == p0 || d == p1 || d == p2 || d == p3 || d == p4) {
                mark2_push(__ldg(src + e));
                int k = atomicAdd(&g_cnt[1], 1);
                if (k < L3CAP) g_list3[k] = e;
            }
        }
    }
}

// ======== phase2: rsqrt-prep + nl2->nl1 (blocks < prepBlocks) ∪ scan2 ========
__global__ __launch_bounds__(256) void k_phase2(
        const int* __restrict__ src, const int* __restrict__ dst,
        int n, int E, int prepBlocks) {
    int t = threadIdx.x;
    int b = blockIdx.x;
    if (b < prepBlocks) {
        int i = (b * 256 + t) * 4;
        if (i + 3 < n) {
            float4 dv = *(float4*)(g_deg + i);
            dv.x = rsqrtf(1.0f + dv.x);
            dv.y = rsqrtf(1.0f + dv.y);
            dv.z = rsqrtf(1.0f + dv.z);
            dv.w = rsqrtf(1.0f + dv.w);
            *(float4*)(g_deg + i) = dv;
        } else {
            for (int j = 0; j < 4; j++)
                if (i + j < n) g_deg[i + j] = rsqrtf(1.0f + g_deg[i + j]);
        }
        // propagate need2 nodes into need1 (self-loop needs their layer-1 output)
        int cnt2n = g_cnt[3]; if (cnt2n > NMAX) cnt2n = NMAX;
        for (int gi = b * 256 + t; gi < cnt2n; gi += prepBlocks * 256)
            mark1_push(g_nl2[gi]);
    } else {
        int bb = b - prepBlocks;
        int base = (bb * 256 + t) * 4;
#pragma unroll
        for (int j = 0; j < 4; j++) {
            int e = base + j;
            if (e >= E) break;
            int d = __ldg(dst + e);
            if ((g_n2bits[d >> 5] >> (d & 31)) & 1u) {
                mark1_push(__ldg(src + e));
                int k = atomicAdd(&g_cnt[0], 1);
                if (k < L2CAP) g_list2[k] = e;
            }
        }
    }
}

// ======== edge1: full scan, warp-cooperative scatter for passing edges ========
__global__ __launch_bounds__(256) void k_edge1(
        const int* __restrict__ src, const int* __restrict__ dst,
        const float* __restrict__ ew, int E) {
    int t = threadIdx.x;
    int lane = t & 31;
    int base = (blockIdx.x * 256 + t) * 4;
#pragma unroll
    for (int j = 0; j < 4; j++) {
        int e = base + j;
        int d = 0;
        bool hit = false;
        if (e < E) {
            d = __ldg(dst + e);
            hit = (g_n1bits[d >> 5] >> (d & 31)) & 1u;
        }
        unsigned m = __ballot_sync(0xffffffffu, hit);
        while (m) {
            int l = __ffs(m) - 1;
            m &= m - 1;
            int es = __shfl_sync(0xffffffffu, e, l);
            int ds = __shfl_sync(0xffffffffu, d, l);
            int ss = __ldg(src + es);                       // uniform addr -> broadcast
            float nrm = g_deg[ss] * __ldg(ew + es) * g_deg[ds];
            if (lane < HDIM)
                atomicAdd(&g_agg1[ds * HDIM + lane], nrm * g_h1p[ss * HDIM + lane]);
        }
    }
}

// ======== node1 (compact): h1 = relu(agg1 + dinv^2*h1p + b1); h2p = h1 @ W2 ========
__global__ __launch_bounds__(256) void k_node1(const float* __restrict__ b1,
                                               const float* __restrict__ W2) {
    __shared__ float w2s[HDIM * HDIM];
    __shared__ float b1s[HDIM];
    int t = threadIdx.x;
    w2s[t] = W2[t];
    if (t < HDIM) b1s[t] = b1[t];
    __syncthreads();
    int cnt = g_cnt[2]; if (cnt > NMAX) cnt = NMAX;
    int stride = gridDim.x * blockDim.x;
    for (int i = blockIdx.x * blockDim.x + t; i < cnt; i += stride) {
        int nd = g_nl1[i];
        float di = g_deg[nd];
        float d2 = di * di;
        float h[HDIM];
        const float4* ar = (const float4*)(g_agg1 + nd * HDIM);
        const float4* hr = (const float4*)(g_h1p + nd * HDIM);
#pragma unroll
        for (int v = 0; v < 4; v++) {
            float4 a = ar[v], p = hr[v];
            h[v*4+0] = fmaxf(a.x + d2 * p.x + b1s[v*4+0], 0.f);
            h[v*4+1] = fmaxf(a.y + d2 * p.y + b1s[v*4+1], 0.f);
            h[v*4+2] = fmaxf(a.z + d2 * p.z + b1s[v*4+2], 0.f);
            h[v*4+3] = fmaxf(a.w + d2 * p.w + b1s[v*4+3], 0.f);
        }
        float* outp = g_h2p + nd * HDIM;
#pragma unroll
        for (int og = 0; og < HDIM; og += 4) {
            float4 acc = make_float4(0.f, 0.f, 0.f, 0.f);
#pragma unroll
            for (int k = 0; k < HDIM; k++) {
                const float* wr = w2s + k * HDIM + og;
                acc.x = fmaf(h[k], wr[0], acc.x);
                acc.y = fmaf(h[k], wr[1], acc.y);
                acc.z = fmaf(h[k], wr[2], acc.z);
                acc.w = fmaf(h[k], wr[3], acc.w);
            }
            *(float4*)(outp + og) = acc;
        }
    }
}

// ======== edge2: thread per (edge,k) over compact list2 ========
__global__ __launch_bounds__(256) void k_edge2(const int* __restrict__ src,
                                               const int* __restrict__ dst,
                                               const float* __restrict__ ew) {
    int cnt = g_cnt[0]; if (cnt > L2CAP) cnt = L2CAP;
    int total = cnt * HDIM;
    int stride = gridDim.x * blockDim.x;
    for (int i = blockIdx.x * blockDim.x + threadIdx.x; i < total; i += stride) {
        int e = g_list2[i >> 4];
        int k = i & 15;
        int s = __ldg(src + e), d = __ldg(dst + e);
        float nrm = g_deg[s] * __ldg(ew + e) * g_deg[d];
        atomicAdd(&g_agg2[d * HDIM + k], nrm * g_h2p[s * HDIM + k]);
    }
}

// ======== node2 (compact): h2 = relu(agg2 + dinv^2*h2p + b2) ========
__global__ __launch_bounds__(256) void k_node2(const float* __restrict__ b2) {
    int cnt = g_cnt[3]; if (cnt > NMAX) cnt = NMAX;
    int stride = gridDim.x * blockDim.x;
    for (int i = blockIdx.x * blockDim.x + threadIdx.x; i < cnt; i += stride) {
        int nd = g_nl2[i];
        float di = g_deg[nd];
        float d2 = di * di;
        const float4* ar = (const float4*)(g_agg2 + nd * HDIM);
        const float4* pr = (const float4*)(g_h2p + nd * HDIM);
        float4* outp = (float4*)(g_h2 + nd * HDIM);
#pragma unroll
        for (int v = 0; v < 4; v++) {
            float4 a = ar[v], p = pr[v];
            float4 o;
            o.x = fmaxf(a.x + d2 * p.x + __ldg(b2 + v*4+0), 0.f);
            o.y = fmaxf(a.y + d2 * p.y + __ldg(b2 + v*4+1), 0.f);
            o.z = fmaxf(a.z + d2 * p.z + __ldg(b2 + v*4+2), 0.f);
            o.w = fmaxf(a.w + d2 * p.w + __ldg(b2 + v*4+3), 0.f);
            outp[v] = o;
        }
    }
}

// ======== edge3: thread per (edge,k) over compact list3 into agg3 ========
__global__ __launch_bounds__(256) void k_edge3(const int* __restrict__ src,
                                               const int* __restrict__ dst,
                                               const float* __restrict__ ew,
                                               const int* __restrict__ pos) {
    int cnt = g_cnt[1]; if (cnt > L3CAP) cnt = L3CAP;
    int total = cnt * HDIM;
    int stride = gridDim.x * blockDim.x;
    for (int i = blockIdx.x * blockDim.x + threadIdx.x; i < total; i += stride) {
        int e = g_list3[i >> 4];
        int k = i & 15;
        int s = __ldg(src + e), d = __ldg(dst + e);
        float nrm = g_deg[s] * __ldg(ew + e) * g_deg[d];
        float val = nrm * g_h2[s * HDIM + k];
#pragma unroll
        for (int a = 0; a < AA; a++)
            if (d == __ldg(pos + a))
                atomicAdd(&g_agg3[a * HDIM + k], val);
    }
}

// ======== head ========
__global__ void k_head(const int* __restrict__ pos,
                       const float* __restrict__ W3, const float* __restrict__ b3,
                       const float* __restrict__ fcW1, const float* __restrict__ fcb1,
                       const float* __restrict__ fcW2, const float* __restrict__ fcb2,
                       const float* __restrict__ fcW3, const float* __restrict__ fcb3,
                       float* __restrict__ out) {
    __shared__ float v[AA * HDIM];
    __shared__ float z[AA * EMB];
    __shared__ float o1[HID];
    __shared__ float o2[HID];
    int t = threadIdx.x;

    if (t < AA * HDIM) {
        int a = t >> 4, k = t & 15;
        int p = __ldg(pos + a);
        float val = 0.0f;
        if (p >= 0) {
            float di = g_deg[p];
            val = g_agg3[t] + di * di * g_h2[p * HDIM + k];
        }
        v[t] = val;
    }
    __syncthreads();

    for (int j = t; j < AA * EMB; j += blockDim.x) {
        int a = j / EMB, c = j % EMB;
        int p = __ldg(pos + a);
        float acc;
        if (p < 0) {
            acc = -1.0f;
        } else {
            acc = __ldg(b3 + c);
#pragma unroll
            for (int k = 0; k < HDIM; k++)
                acc = fmaf(v[a * HDIM + k], __ldg(W3 + k * EMB + c), acc);
        }
        z[j] = acc;
    }
    __syncthreads();

    if (t < HID) {
        float acc = __ldg(fcb1 + t);
#pragma unroll 4
        for (int j = 0; j < AA * EMB; j++)
            acc = fmaf(z[j], __ldg(fcW1 + j * HID + t), acc);
        o1[t] = fmaxf(acc, 0.0f);
    }
    __syncthreads();

    if (t < HID) {
        float acc = __ldg(fcb2 + t);
#pragma unroll 4
        for (int j = 0; j < HID; j++)
            acc = fmaf(o1[j], __ldg(fcW2 + j * HID + t), acc);
        o2[t] = fmaxf(acc, 0.0f);
    }
    __syncthreads();

    if (t < AA) {
        float acc = __ldg(fcb3 + t);
#pragma unroll 4
        for (int j = 0; j < HID; j++)
            acc = fmaf(o2[j], __ldg(fcW3 + j * AA + t), acc);
        out[t] = acc;
    }
}

extern "C" void kernel_launch(void* const* d_in, const int* in_sizes, int n_in,
                              void* d_out, int out_size) {
    const float* x    = (const float*)d_in[0];
    const int*   ei   = (const int*)  d_in[1];
    const float* ew   = (const float*)d_in[2];
    const int*   pos  = (const int*)  d_in[3];
    const float* W1   = (const float*)d_in[4];
    const float* b1   = (const float*)d_in[5];
    const float* W2   = (const float*)d_in[6];
    const float* b2   = (const float*)d_in[7];
    const float* W3   = (const float*)d_in[8];
    const float* b3   = (const float*)d_in[9];
    const float* fcW1 = (const float*)d_in[10];
    const float* fcb1 = (const float*)d_in[11];
    const float* fcW2 = (const float*)d_in[12];
    const float* fcb2 = (const float*)d_in[13];
    const float* fcW3 = (const float*)d_in[14];
    const float* fcb3 = (const float*)d_in[15];

    int N = in_sizes[0] / F_IN;
    int E = in_sizes[1] / 2;
    const int* src = ei;
    const int* dst = ei + E;
    float* out = (float*)d_out;

    void *a_deg, *a_n1, *a_n2, *a_cnt, *a_agg3;
    cudaGetSymbolAddress(&a_deg,  g_deg);
    cudaGetSymbolAddress(&a_n1,   g_n1bits);
    cudaGetSymbolAddress(&a_n2,   g_n2bits);
    cudaGetSymbolAddress(&a_cnt,  g_cnt);
    cudaGetSymbolAddress(&a_agg3, g_agg3);

    cudaMemsetAsync(a_deg,  0, (size_t)N * sizeof(float));
    cudaMemsetAsync(a_n1,   0, NB * sizeof(unsigned int));
    cudaMemsetAsync(a_n2,   0, NB * sizeof(unsigned int));
    cudaMemsetAsync(a_cnt,  0, 4 * sizeof(int));
    cudaMemsetAsync(a_agg3, 0, AA * HDIM * sizeof(float));

    int gemmBlocks = (N + GN - 1) / GN;                 // 1563
    int scanBlocks = (E + 4 * 256 - 1) / (4 * 256);     // 3125
    int prepBlocks = (N + 4 * 256 - 1) / (4 * 256);     // 98

    k_phase1<<<gemmBlocks + scanBlocks, 256>>>(x, W1, src, dst, ew, pos, N, E, gemmBlocks);
    k_phase2<<<prepBlocks + scanBlocks, 256>>>(src, dst, N, E, prepBlocks);
    k_edge1 <<<scanBlocks, 256>>>(src, dst, ew, E);
    k_node1 <<<32, 256>>>(b1, W2);
    k_edge2 <<<64, 256>>>(src, dst, ew);
    k_node2 <<<4, 256>>>(b2);
    k_edge3 <<<8, 256>>>(src, dst, ew, pos);
    k_head  <<<1, 128>>>(pos, W3, b3, fcW1, fcb1, fcW2, fcb2, fcW3, fcb3, out);
}